// round 1
// baseline (speedup 1.0000x reference)
#include <cuda_runtime.h>
#include <stdint.h>

#define NN 50000
#define EE 800000
#define EP (NN + EE)
#define DD 64
#define HH 4
#define CC 16
#define LL 3
#define SCAN_B 1024
#define NBLK ((NN + SCAN_B - 1) / SCAN_B)

// ---------------- scratch (device globals: no allocation allowed) ----------------
__device__ __align__(16) float g_h[NN * DD];
__device__ __align__(16) float g_h0[NN * DD];
__device__ __align__(16) float g_xl[NN * DD];
__device__ __align__(16) float g_xr[NN * DD];
__device__ __align__(16) float g_res[NN * DD];
__device__ int g_deg[NN];
__device__ int g_scan[NN];
__device__ int g_rowptr[NN + 1];
__device__ int g_cursor[NN];
__device__ int g_col[EP];
__device__ int g_bsum[64];
__device__ int g_bsumex[64];

// ---------------- input projection: h = relu(x@Wt+bt); h = [h, Et[type]]@Wp + bp ----------------
__global__ void k_input(const float* __restrict__ x, const int* __restrict__ node_type,
                        const float* __restrict__ Wt, const float* __restrict__ bt,
                        const float* __restrict__ Et, const float* __restrict__ Wp,
                        const float* __restrict__ bp) {
    __shared__ float tmp[4][DD];
    int nl = threadIdx.x >> 6;          // 0..3 node within block
    int c  = threadIdx.x & 63;          // channel
    int node = blockIdx.x * 4 + nl;
    float a = 0.f;
    if (node < NN) {
        a = bt[c];
        #pragma unroll
        for (int f = 0; f < 8; f++) a += x[node * 8 + f] * Wt[f * DD + c];
        tmp[nl][c] = fmaxf(a, 0.f);
    }
    __syncthreads();
    if (node < NN) {
        int t = node_type[node];
        float b = bp[c];
        #pragma unroll
        for (int k = 0; k < DD; k++) b += tmp[nl][k] * Wp[k * DD + c];
        #pragma unroll
        for (int j = 0; j < 16; j++) b += Et[t * 16 + j] * Wp[(DD + j) * DD + c];
        g_h[node * DD + c]  = b;
        g_h0[node * DD + c] = b;
    }
}

// ---------------- CSR build ----------------
__global__ void k_deg_init() {
    int i = blockIdx.x * 256 + threadIdx.x;
    if (i < NN) g_deg[i] = 1;           // self loop
}
__global__ void k_count(const int* __restrict__ edst) {
    int i = blockIdx.x * 256 + threadIdx.x;
    if (i < EE) atomicAdd(&g_deg[edst[i]], 1);
}
__global__ void k_scan1() {
    __shared__ int sm[SCAN_B];
    int i = blockIdx.x * SCAN_B + threadIdx.x;
    int v = (i < NN) ? g_deg[i] : 0;
    sm[threadIdx.x] = v;
    __syncthreads();
    for (int ofs = 1; ofs < SCAN_B; ofs <<= 1) {
        int t = (threadIdx.x >= ofs) ? sm[threadIdx.x - ofs] : 0;
        __syncthreads();
        sm[threadIdx.x] += t;
        __syncthreads();
    }
    if (i < NN) g_scan[i] = sm[threadIdx.x];
    if (threadIdx.x == SCAN_B - 1) g_bsum[blockIdx.x] = sm[SCAN_B - 1];
}
__global__ void k_scan2() {
    __shared__ int sm[64];
    int v = (threadIdx.x < NBLK) ? g_bsum[threadIdx.x] : 0;
    sm[threadIdx.x] = v;
    __syncthreads();
    for (int ofs = 1; ofs < 64; ofs <<= 1) {
        int t = (threadIdx.x >= ofs) ? sm[threadIdx.x - ofs] : 0;
        __syncthreads();
        sm[threadIdx.x] += t;
        __syncthreads();
    }
    g_bsumex[threadIdx.x] = sm[threadIdx.x] - v;  // exclusive
}
__global__ void k_scan3() {
    int i = blockIdx.x * 256 + threadIdx.x;
    if (i < NN) {
        int ex = g_scan[i] - g_deg[i] + g_bsumex[i / SCAN_B];
        g_rowptr[i] = ex;
        g_cursor[i] = ex;
    }
    if (i == 0) g_rowptr[NN] = EP;
}
__global__ void k_scatter(const int* __restrict__ esrc, const int* __restrict__ edst) {
    int i = blockIdx.x * 256 + threadIdx.x;
    if (i < EE) {
        int pos = atomicAdd(&g_cursor[edst[i]], 1);
        g_col[pos] = esrc[i];
    } else if (i < EP) {
        int n = i - EE;
        int pos = atomicAdd(&g_cursor[n], 1);
        g_col[pos] = n;
    }
}

// ---------------- fused 3x GEMM: xl = h@Wl+bl, xr = h@Wr+br, res = h@Wres+bconv ----------------
__global__ void k_gemm3(const float* __restrict__ Wl, const float* __restrict__ bl,
                        const float* __restrict__ Wr, const float* __restrict__ br,
                        const float* __restrict__ Ws, const float* __restrict__ bs) {
    __shared__ float hs[32][DD];
    int base = blockIdx.x * 32;
    int t = threadIdx.x;
    for (int i = t; i < 32 * DD; i += 256) {
        int r = i >> 6, c = i & 63;
        int node = base + r;
        hs[r][c] = (node < NN) ? g_h[node * DD + c] : 0.f;
    }
    __syncthreads();
    int tc = t & 63;
    int tn = t >> 6;  // 0..3
    float aL[8] = {}, aR[8] = {}, aS[8] = {};
    #pragma unroll 8
    for (int k = 0; k < DD; k++) {
        float wl = Wl[k * DD + tc], wr = Wr[k * DD + tc], ws = Ws[k * DD + tc];
        #pragma unroll
        for (int j = 0; j < 8; j++) {
            float hv = hs[tn + 4 * j][k];
            aL[j] += hv * wl; aR[j] += hv * wr; aS[j] += hv * ws;
        }
    }
    float bL = bl[tc], bR = br[tc], bS = bs[tc];
    #pragma unroll
    for (int j = 0; j < 8; j++) {
        int node = base + tn + 4 * j;
        if (node < NN) {
            g_xl[node * DD + tc]  = aL[j] + bL;
            g_xr[node * DD + tc]  = aR[j] + bR;
            g_res[node * DD + tc] = aS[j] + bS;
        }
    }
}

// ---------------- GAT aggregation + residual + LayerNorm (warp per dst node) ----------------
__device__ __forceinline__ float dl4(float4 x, float4 r, float4 a) {
    float e, s;
    e = x.x + r.x; e = fmaxf(e, 0.2f * e); s  = e * a.x;
    e = x.y + r.y; e = fmaxf(e, 0.2f * e); s += e * a.y;
    e = x.z + r.z; e = fmaxf(e, 0.2f * e); s += e * a.z;
    e = x.w + r.w; e = fmaxf(e, 0.2f * e); s += e * a.w;
    return s;
}
__device__ __forceinline__ void sc4(float4& c, float f) { c.x *= f; c.y *= f; c.z *= f; c.w *= f; }
__device__ __forceinline__ void fma4(float4& c, float w, float4 x) {
    c.x += w * x.x; c.y += w * x.y; c.z += w * x.z; c.w += w * x.w;
}
__device__ __forceinline__ float4 wred4(float4 v) {
    #pragma unroll
    for (int o = 4; o < 32; o <<= 1) {
        v.x += __shfl_xor_sync(0xffffffffu, v.x, o);
        v.y += __shfl_xor_sync(0xffffffffu, v.y, o);
        v.z += __shfl_xor_sync(0xffffffffu, v.z, o);
        v.w += __shfl_xor_sync(0xffffffffu, v.w, o);
    }
    return v;
}

__global__ void k_gat(const float* __restrict__ att, const float* __restrict__ gamma,
                      const float* __restrict__ beta, const float* __restrict__ alpha_p) {
    __shared__ float sout[8][DD];
    int gw = (blockIdx.x * blockDim.x + threadIdx.x) >> 5;
    if (gw >= NN) return;                       // uniform per warp
    int lane = threadIdx.x & 31;
    int wib  = threadIdx.x >> 5;
    int node = gw;
    int head = lane & 3;
    int el   = lane >> 2;                        // edge slot 0..7
    const float NEG_INF = __int_as_float(0xff800000);

    const float4* xrp = (const float4*)(g_xr + node * DD + head * CC);
    float4 r0 = xrp[0], r1 = xrp[1], r2 = xrp[2], r3 = xrp[3];
    const float4* ap = (const float4*)(att + head * CC);
    float4 a0 = ap[0], a1 = ap[1], a2 = ap[2], a3 = ap[3];

    float m = NEG_INF, s = 0.f;
    float4 c0 = {0, 0, 0, 0}, c1 = c0, c2 = c0, c3 = c0;

    int beg = g_rowptr[node], end = g_rowptr[node + 1];
    for (int j = beg; j < end; j += 8) {
        int idx = j + el;
        bool v = idx < end;
        int src = v ? g_col[idx] : node;
        const float4* xp = (const float4*)(g_xl + src * DD + head * CC);
        float4 x0 = xp[0], x1 = xp[1], x2 = xp[2], x3 = xp[3];
        float p = dl4(x0, r0, a0) + dl4(x1, r1, a1) + dl4(x2, r2, a2) + dl4(x3, r3, a3);
        if (!v) p = NEG_INF;
        float bm = p;
        bm = fmaxf(bm, __shfl_xor_sync(0xffffffffu, bm, 4));
        bm = fmaxf(bm, __shfl_xor_sync(0xffffffffu, bm, 8));
        bm = fmaxf(bm, __shfl_xor_sync(0xffffffffu, bm, 16));
        if (bm > m) {                             // uniform within head group
            float sc = __expf(m - bm);            // m==-inf -> 0 (s,acc are 0 then)
            s *= sc;
            sc4(c0, sc); sc4(c1, sc); sc4(c2, sc); sc4(c3, sc);
            m = bm;
        }
        float w = __expf(p - m);                  // invalid -> exp(-inf)=0
        s += w;
        fma4(c0, w, x0); fma4(c1, w, x1); fma4(c2, w, x2); fma4(c3, w, x3);
    }
    // reduce across the 8 edge-slot lanes of each head group
    #pragma unroll
    for (int o = 4; o < 32; o <<= 1) s += __shfl_xor_sync(0xffffffffu, s, o);
    c0 = wred4(c0); c1 = wred4(c1); c2 = wred4(c2); c3 = wred4(c3);
    float inv = 1.f / (s + 1e-16f);

    if (el == 0) {                                // lanes 0..3 hold heads 0..3
        float4* so = (float4*)&sout[wib][head * CC];
        so[0] = make_float4(c0.x * inv, c0.y * inv, c0.z * inv, c0.w * inv);
        so[1] = make_float4(c1.x * inv, c1.y * inv, c1.z * inv, c1.w * inv);
        so[2] = make_float4(c2.x * inv, c2.y * inv, c2.z * inv, c2.w * inv);
        so[3] = make_float4(c3.x * inv, c3.y * inv, c3.z * inv, c3.w * inv);
    }
    __syncwarp();

    // residual + alpha blend + LayerNorm (2 channels per lane)
    float alpha = *alpha_p;
    int cch = lane * 2;
    float t0 = sout[wib][cch]     + g_res[node * DD + cch];
    float t1 = sout[wib][cch + 1] + g_res[node * DD + cch + 1];
    t0 = alpha * t0 + (1.f - alpha) * g_h0[node * DD + cch];
    t1 = alpha * t1 + (1.f - alpha) * g_h0[node * DD + cch + 1];
    float sum = t0 + t1;
    #pragma unroll
    for (int o = 1; o < 32; o <<= 1) sum += __shfl_xor_sync(0xffffffffu, sum, o);
    float mean = sum * (1.f / 64.f);
    float d0 = t0 - mean, d1 = t1 - mean;
    float vs = d0 * d0 + d1 * d1;
    #pragma unroll
    for (int o = 1; o < 32; o <<= 1) vs += __shfl_xor_sync(0xffffffffu, vs, o);
    float rstd = rsqrtf(vs * (1.f / 64.f) + 1e-5f);
    g_h[node * DD + cch]     = gamma[cch]     * d0 * rstd + beta[cch];
    g_h[node * DD + cch + 1] = gamma[cch + 1] * d1 * rstd + beta[cch + 1];
}

// ---------------- output head: sigmoid(relu(h@W1+b1)@W2+b2), warp per node ----------------
__global__ void k_head(const float* __restrict__ W1, const float* __restrict__ b1,
                       const float* __restrict__ W2, const float* __restrict__ b2,
                       float* __restrict__ out) {
    __shared__ float sh[8][DD];
    int gw = (blockIdx.x * blockDim.x + threadIdx.x) >> 5;
    if (gw >= NN) return;
    int lane = threadIdx.x & 31;
    int wib  = threadIdx.x >> 5;
    sh[wib][lane]      = g_h[gw * DD + lane];
    sh[wib][lane + 32] = g_h[gw * DD + lane + 32];
    __syncwarp();
    float z = b1[lane];
    #pragma unroll
    for (int k = 0; k < DD; k++) z += sh[wib][k] * W1[k * 32 + lane];
    z = fmaxf(z, 0.f);
    float ps = z * W2[lane];
    #pragma unroll
    for (int o = 1; o < 32; o <<= 1) ps += __shfl_xor_sync(0xffffffffu, ps, o);
    if (lane == 0) out[gw] = 1.f / (1.f + __expf(-(ps + b2[0])));
}

// ---------------- launch ----------------
extern "C" void kernel_launch(void* const* d_in, const int* in_sizes, int n_in,
                              void* d_out, int out_size) {
    const float* x         = (const float*)d_in[0];
    const int*   node_type = (const int*)d_in[1];
    const int*   esrc      = (const int*)d_in[2];
    const int*   edst      = (const int*)d_in[3];
    const float* Wt        = (const float*)d_in[4];
    const float* bt        = (const float*)d_in[5];
    const float* Et        = (const float*)d_in[6];
    const float* Wp        = (const float*)d_in[7];
    const float* bp        = (const float*)d_in[8];
    const float* Wl        = (const float*)d_in[9];
    const float* bl        = (const float*)d_in[10];
    const float* Wr        = (const float*)d_in[11];
    const float* br        = (const float*)d_in[12];
    const float* att       = (const float*)d_in[13];
    const float* Wres      = (const float*)d_in[14];
    const float* bconv     = (const float*)d_in[15];
    const float* gamma     = (const float*)d_in[16];
    const float* beta      = (const float*)d_in[17];
    const float* alpha     = (const float*)d_in[18];
    const float* W1        = (const float*)d_in[19];
    const float* b1        = (const float*)d_in[20];
    const float* W2        = (const float*)d_in[21];
    const float* b2        = (const float*)d_in[22];
    float* out = (float*)d_out;

    k_input<<<(NN + 3) / 4, 256>>>(x, node_type, Wt, bt, Et, Wp, bp);
    k_deg_init<<<(NN + 255) / 256, 256>>>();
    k_count<<<(EE + 255) / 256, 256>>>(edst);
    k_scan1<<<NBLK, SCAN_B>>>();
    k_scan2<<<1, 64>>>();
    k_scan3<<<(NN + 255) / 256, 256>>>();
    k_scatter<<<(EP + 255) / 256, 256>>>(esrc, edst);

    for (int l = 0; l < LL; l++) {
        k_gemm3<<<(NN + 31) / 32, 256>>>(Wl + l * DD * DD, bl + l * DD,
                                         Wr + l * DD * DD, br + l * DD,
                                         Wres + l * DD * DD, bconv + l * DD);
        k_gat<<<(NN + 7) / 8, 256>>>(att + l * HH * CC, gamma + l * DD, beta + l * DD, alpha);
    }
    k_head<<<(NN + 7) / 8, 256>>>(W1, b1, W2, b2, out);
}